// round 14
// baseline (speedup 1.0000x reference)
#include <cuda_runtime.h>
#include <cmath>

#define NMAX 20000

__device__ float  g_PHI[NMAX * 32];
__device__ float  g_ENV[NMAX];
__device__ float  g_F[NMAX * 192];
__device__ float4 g_WQ[6 * 16 * 64];   // [mat][c4][o] = W[o][4c4..4c4+3]

// ---------------------------------------------------------------------------
// Edge kernel (R4-proven artifact): scatter env-weighted RBF vector + env.
// ---------------------------------------------------------------------------
__global__ void edge_kernel(const float* __restrict__ dist,
                            const int* __restrict__ nb, int E,
                            float mu0, float delta, float inv_delta,
                            float beta, float c2, float q)
{
    int e = blockIdx.x * blockDim.x + threadIdx.x;
    if (e >= E) return;
    float d = dist[e];
    int j = nb[e];
    float env = 0.0f;
    if (d < 5.0f) env = 0.5f * (__cosf(0.62831853071795864769f * d) + 1.0f);
    atomicAdd(&g_ENV[j], env);

    float t = __expf(-d);
    int r0 = (int)floorf((t - mu0) * inv_delta + 0.5f);
    r0 = max(0, min(31, r0));
    float u0 = t - (mu0 + delta * (float)r0);
    float p0 = env * __expf(-beta * u0 * u0);
    float* phr = g_PHI + (size_t)j * 32;
    const float THR = 1e-6f;
    if (p0 > THR) atomicAdd(&phr[r0], p0);

    float w = __expf(c2 * (t - (mu0 + delta * ((float)r0 + 0.5f))));
    float p = p0;
    for (int r = r0 + 1; r < 32; ++r) {
        p *= w; w *= q;
        if (p <= THR) break;
        atomicAdd(&phr[r], p);
    }
    w = __expf(-c2 * (t - (mu0 + delta * ((float)r0 - 0.5f))));
    p = p0;
    for (int r = r0 - 1; r >= 0; --r) {
        p *= w; w *= q;
        if (p <= THR) break;
        atomicAdd(&phr[r], p);
    }
}

// ---------------------------------------------------------------------------
// Transform kernel: repack 6 weight matrices into [c4][o] float4 layout so a
// warp's 32 lanes read consecutive 16B chunks (coalesced LDG.128, L1-resident).
// ---------------------------------------------------------------------------
__global__ void wq_kernel(const float* __restrict__ W0, const float* __restrict__ W1,
                          const float* __restrict__ W2, const float* __restrict__ W3,
                          const float* __restrict__ W4, const float* __restrict__ W5)
{
    int m = blockIdx.x;          // 0..5
    int idx = threadIdx.x;       // 0..1023
    const float* Wsel = (m == 0) ? W0 : (m == 1) ? W1 : (m == 2) ? W2
                      : (m == 3) ? W3 : (m == 4) ? W4 : W5;
    int c4 = idx >> 6;           // 0..15
    int o  = idx & 63;
    const float4* src = (const float4*)(Wsel + o * 64 + c4 * 4);
    g_WQ[m * 1024 + idx] = *src;
}

// ---------------------------------------------------------------------------
// Coefficient kernel v2 (block-tiled): Wd rows held in registers; Wd read from
// DRAM only grid-many times (3.8MB total, not 480MB).
// F[n,o] = env[n]*bd[o] + Wd[o,:] . phi[n,:]
// ---------------------------------------------------------------------------
#define COEFF_NB 128
__global__ void coeff_kernel(const float* __restrict__ Wd,
                             const float* __restrict__ bd, int N)
{
    __shared__ float ph[2][33];
    int o = threadIdx.x;         // 0..191
    float wreg[32];
    const float4* wsrc = (const float4*)(Wd + (size_t)o * 32);
    #pragma unroll
    for (int i = 0; i < 8; ++i) {
        float4 v = wsrc[i];
        wreg[4 * i] = v.x; wreg[4 * i + 1] = v.y;
        wreg[4 * i + 2] = v.z; wreg[4 * i + 3] = v.w;
    }
    float b = bd[o];
    int nstart = blockIdx.x * COEFF_NB;
    int nend = min(nstart + COEFF_NB, N);
    for (int n = nstart; n < nend; ++n) {
        int buf = n & 1;
        if (o < 32) ph[buf][o] = g_PHI[(size_t)n * 32 + o];
        if (o == 32) ph[buf][32] = g_ENV[n];
        __syncthreads();
        float acc = ph[buf][32] * b;
        #pragma unroll
        for (int r = 0; r < 32; ++r) acc += wreg[r] * ph[buf][r];
        g_F[(size_t)n * 192 + o] = acc;
    }
}

// ---------------------------------------------------------------------------
// f32x2 packed FMA helpers
// ---------------------------------------------------------------------------
__device__ __forceinline__ void ffma2(unsigned long long& d,
                                      unsigned long long a,
                                      unsigned long long b)
{
    asm("fma.rn.f32x2 %0, %1, %2, %0;" : "+l"(d) : "l"(a), "l"(b));
}
__device__ __forceinline__ float sum2(unsigned long long v)
{
    float lo, hi;
    asm("mov.b64 {%0, %1}, %2;" : "=f"(lo), "=f"(hi) : "l"(v));
    return lo + hi;
}
__device__ __forceinline__ void split4(float4 v, unsigned long long& lo,
                                       unsigned long long& hi)
{
    asm("mov.b64 %0, {%2, %3}; mov.b64 %1, {%4, %5};"
        : "=l"(lo), "=l"(hi) : "f"(v.x), "f"(v.y), "f"(v.z), "f"(v.w));
}

__device__ __forceinline__ void decomp9(const float x[9], float* iso,
                                        float a[3], float s[5])
{
    float m = (x[0] + x[4] + x[8]) * (1.0f / 3.0f);
    *iso = m;
    a[0] = 0.5f * (x[1] - x[3]);
    a[1] = 0.5f * (x[2] - x[6]);
    a[2] = 0.5f * (x[5] - x[7]);
    s[0] = x[0] - m;
    s[1] = 0.5f * (x[1] + x[3]);
    s[2] = 0.5f * (x[2] + x[6]);
    s[3] = x[4] - m;
    s[4] = 0.5f * (x[5] + x[7]);
}

__device__ __forceinline__ void build9(float iso, const float a[3],
                                       const float s[5], float Y[9])
{
    Y[0] = iso + s[0];        Y[1] = a[0] + s[1];       Y[2] = a[1] + s[2];
    Y[3] = s[1] - a[0];       Y[4] = iso + s[3];        Y[5] = a[2] + s[4];
    Y[6] = s[2] - a[1];       Y[7] = s[4] - a[2];       Y[8] = iso - s[0] - s[3];
}

// ---------------------------------------------------------------------------
// Node kernel: 256 threads = 4 pairs, GRP=2 nodes/pair, 3 blocks/SM (24 warps).
// No smem weights: mixes read g_WQ (coalesced LDG.128, L1-resident).
// K-split (warp0: A planes 0-2 + iso 8; warp1: S planes 3-7).
// M preserved via out-scratch (same-thread write/read; R13-verified).
// ---------------------------------------------------------------------------
#define GRP 2
#define PLANE 68
#define CPSZ (9 * PLANE)            // 612 per node
#define PSZ 1808                    // cp 2*612=1224 | xs 576 | pad 8
#define SMEM_FLOATS (4 * PSZ)       // 7232 floats = 28,928 B per block

#define PAIR_BAR() asm volatile("bar.sync %0, 64;" :: "r"(barid) : "memory")

__device__ __forceinline__ void mix_stage(const float4* __restrict__ WQA,
                                          const float4* __restrict__ WQS,
                                          const float4* __restrict__ WQI,
                                          float* __restrict__ cp,
                                          int lane, int half)
{
    if (half == 0) {
        unsigned long long accA[3][2][GRP] = {};
        unsigned long long accI[2][GRP] = {};
        #pragma unroll 4
        for (int j = 0; j < 16; ++j) {
            unsigned long long a0x, a0y, a1x, a1y, i0x, i0y, i1x, i1y;
            split4(__ldg(&WQA[j * 64 + lane]),      a0x, a0y);
            split4(__ldg(&WQA[j * 64 + lane + 32]), a1x, a1y);
            split4(__ldg(&WQI[j * 64 + lane]),      i0x, i0y);
            split4(__ldg(&WQI[j * 64 + lane + 32]), i1x, i1y);
            #pragma unroll
            for (int n = 0; n < GRP; ++n) {
                const float* base = cp + n * CPSZ + 4 * j;
                #pragma unroll
                for (int k = 0; k < 3; ++k) {
                    ulonglong2 m = *(const ulonglong2*)(base + k * PLANE);
                    ffma2(accA[k][0][n], a0x, m.x);
                    ffma2(accA[k][0][n], a0y, m.y);
                    ffma2(accA[k][1][n], a1x, m.x);
                    ffma2(accA[k][1][n], a1y, m.y);
                }
                ulonglong2 m8 = *(const ulonglong2*)(base + 8 * PLANE);
                ffma2(accI[0][n], i0x, m8.x);
                ffma2(accI[0][n], i0y, m8.y);
                ffma2(accI[1][n], i1x, m8.x);
                ffma2(accI[1][n], i1y, m8.y);
            }
        }
        __syncwarp();
        #pragma unroll
        for (int n = 0; n < GRP; ++n) {
            float* cpn = cp + n * CPSZ;
            #pragma unroll
            for (int h = 0; h < 2; ++h) {
                int ch = lane + 32 * h;
                cpn[0 * PLANE + ch] = sum2(accA[0][h][n]);
                cpn[1 * PLANE + ch] = sum2(accA[1][h][n]);
                cpn[2 * PLANE + ch] = sum2(accA[2][h][n]);
                cpn[8 * PLANE + ch] = sum2(accI[h][n]);
            }
        }
    } else {
        unsigned long long accS[5][2][GRP] = {};
        #pragma unroll 4
        for (int j = 0; j < 16; ++j) {
            unsigned long long s0x, s0y, s1x, s1y;
            split4(__ldg(&WQS[j * 64 + lane]),      s0x, s0y);
            split4(__ldg(&WQS[j * 64 + lane + 32]), s1x, s1y);
            #pragma unroll
            for (int n = 0; n < GRP; ++n) {
                const float* base = cp + n * CPSZ + 3 * PLANE + 4 * j;
                #pragma unroll
                for (int k = 0; k < 5; ++k) {
                    ulonglong2 m = *(const ulonglong2*)(base + k * PLANE);
                    ffma2(accS[k][0][n], s0x, m.x);
                    ffma2(accS[k][0][n], s0y, m.y);
                    ffma2(accS[k][1][n], s1x, m.x);
                    ffma2(accS[k][1][n], s1y, m.y);
                }
            }
        }
        __syncwarp();
        #pragma unroll
        for (int n = 0; n < GRP; ++n) {
            float* cpn = cp + n * CPSZ;
            #pragma unroll
            for (int h = 0; h < 2; ++h) {
                int ch = lane + 32 * h;
                #pragma unroll
                for (int k = 0; k < 5; ++k)
                    cpn[(3 + k) * PLANE + ch] = sum2(accS[k][h][n]);
            }
        }
    }
}

__global__ __launch_bounds__(256, 3)
void node_kernel(const float* __restrict__ X, float* __restrict__ out, int N)
{
    extern __shared__ float sm[];
    int tid   = threadIdx.x;
    int lane  = tid & 31;
    int pair  = tid >> 6;             // 0..3
    int half  = (tid >> 5) & 1;
    int c     = lane + 32 * half;     // this thread's channel
    int pid   = tid & 63;
    int barid = pair + 1;             // named barrier per pair (1..4)

    float* cp = sm + pair * PSZ;      // 2 * 612 comp planes
    float* xs = cp + GRP * CPSZ;      // 576 staging

    const float4* WQAa = g_WQ + 0 * 1024;
    const float4* WQSa = g_WQ + 1 * 1024;
    const float4* WQIa = g_WQ + 2 * 1024;
    const float4* WQAb = g_WQ + 3 * 1024;
    const float4* WQSb = g_WQ + 4 * 1024;
    const float4* WQIb = g_WQ + 5 * 1024;

    int Q = (N + GRP - 1) / GRP;
    int gp = blockIdx.x * 4 + pair;
    int step = gridDim.x * 4;

    for (int q = gp; q < Q; q += step) {
        int n0 = q * GRP;

        // ---- coefficients (precomputed) ----
        float fI[GRP], fA[GRP], fS[GRP];
        #pragma unroll
        for (int n = 0; n < GRP; ++n) {
            int node = min(n0 + n, N - 1);
            const float* Fn = g_F + (size_t)node * 192;
            fI[n] = Fn[c];
            fA[n] = Fn[64 + c];
            fS[n] = Fn[128 + c];
        }

        // ---- per node: stage X, decompose -> cp planes + folded-M to out ---
        #pragma unroll
        for (int n = 0; n < GRP; ++n) {
            int node = n0 + n;
            if (node < N) {
                const float4* src = (const float4*)(X + (size_t)node * 576);
                float4* dst = (float4*)xs;
                #pragma unroll
                for (int i = 0; i < 3; ++i) {
                    int idx = pid + 64 * i;
                    if (idx < 144) dst[idx] = src[idx];
                }
            }
            PAIR_BAR();
            if (node < N) {
                float x[9];
                #pragma unroll
                for (int k = 0; k < 9; ++k) x[k] = xs[c * 9 + k];
                float f = 0.0f;
                #pragma unroll
                for (int k = 0; k < 9; ++k) f += x[k] * x[k];
                float sc = __fdividef(1.0f, f + 1.0f);
                #pragma unroll
                for (int k = 0; k < 9; ++k) x[k] *= sc;
                float iso, a[3], s[5];
                decomp9(x, &iso, a, s);
                float* cpn = cp + n * CPSZ;
                cpn[0 * PLANE + c] = a[0];
                cpn[1 * PLANE + c] = a[1];
                cpn[2 * PLANE + c] = a[2];
                cpn[3 * PLANE + c] = s[0];
                cpn[4 * PLANE + c] = s[1];
                cpn[5 * PLANE + c] = s[2];
                cpn[6 * PLANE + c] = s[3];
                cpn[7 * PLANE + c] = s[4];
                cpn[8 * PLANE + c] = iso;
                float* mo = out + (size_t)node * 576;
                mo[0 * 64 + c] = fA[n] * a[0];
                mo[1 * 64 + c] = fA[n] * a[1];
                mo[2 * 64 + c] = fA[n] * a[2];
                mo[3 * 64 + c] = fS[n] * s[0];
                mo[4 * 64 + c] = fS[n] * s[1];
                mo[5 * 64 + c] = fS[n] * s[2];
                mo[6 * 64 + c] = fS[n] * s[3];
                mo[7 * 64 + c] = fS[n] * s[4];
                mo[8 * 64 + c] = fI[n] * iso;
            }
            PAIR_BAR();
        }

        // ---- pre mix (k-split, weights from L1-resident g_WQ) ----
        mix_stage(WQAa, WQSa, WQIa, cp, lane, half);
        PAIR_BAR();

        // ---- sandwich: Z = YM + MY (M from out-scratch), norm, decompose ---
        #pragma unroll
        for (int n = 0; n < GRP; ++n) {
            int node = n0 + n;
            if (node < N) {
                float* cpn = cp + n * CPSZ;
                const float* mo = out + (size_t)node * 576;
                float yv[9], mv[9];
                #pragma unroll
                for (int k = 0; k < 9; ++k) {
                    yv[k] = cpn[k * PLANE + c];
                    mv[k] = mo[k * 64 + c];     // same thread wrote it
                }
                float Y[9], M[9];
                build9(yv[8], &yv[0], &yv[3], Y);
                build9(mv[8], &mv[0], &mv[3], M);
                float Z[9];
                #pragma unroll
                for (int i = 0; i < 3; ++i)
                    #pragma unroll
                    for (int jj = 0; jj < 3; ++jj) {
                        float acc = 0.0f;
                        #pragma unroll
                        for (int k = 0; k < 3; ++k)
                            acc += Y[i * 3 + k] * M[k * 3 + jj]
                                 + M[i * 3 + k] * Y[k * 3 + jj];
                        Z[i * 3 + jj] = acc;
                    }
                float nrm = 0.0f;
                #pragma unroll
                for (int k = 0; k < 9; ++k) { float v = Z[k] + 1.0f; nrm += v * v; }
                float inv = __fdividef(1.0f, nrm);
                #pragma unroll
                for (int k = 0; k < 9; ++k) Z[k] *= inv;
                float iso, a2[3], s2[5];
                decomp9(Z, &iso, a2, s2);
                cpn[0 * PLANE + c] = a2[0];
                cpn[1 * PLANE + c] = a2[1];
                cpn[2 * PLANE + c] = a2[2];
                cpn[3 * PLANE + c] = s2[0];
                cpn[4 * PLANE + c] = s2[1];
                cpn[5 * PLANE + c] = s2[2];
                cpn[6 * PLANE + c] = s2[3];
                cpn[7 * PLANE + c] = s2[4];
                cpn[8 * PLANE + c] = iso;
            }
        }
        PAIR_BAR();

        // ---- post mix ----
        mix_stage(WQAb, WQSb, WQIb, cp, lane, half);
        PAIR_BAR();

        // ---- output: O = Y2 + Y2@Y2, stage per node, pair-coalesced store --
        #pragma unroll
        for (int n = 0; n < GRP; ++n) {
            int node = n0 + n;
            {
                float* cpn = cp + n * CPSZ;
                float yv[9];
                #pragma unroll
                for (int k = 0; k < 9; ++k) yv[k] = cpn[k * PLANE + c];
                float Y2[9];
                build9(yv[8], &yv[0], &yv[3], Y2);
                float* od = xs + c * 9;
                #pragma unroll
                for (int i = 0; i < 3; ++i)
                    #pragma unroll
                    for (int jj = 0; jj < 3; ++jj) {
                        float acc = Y2[i * 3 + jj];
                        #pragma unroll
                        for (int k = 0; k < 3; ++k)
                            acc += Y2[i * 3 + k] * Y2[k * 3 + jj];
                        od[i * 3 + jj] = acc;
                    }
            }
            PAIR_BAR();
            if (node < N) {
                float4* dst = (float4*)(out + (size_t)node * 576);
                const float4* src = (const float4*)xs;
                #pragma unroll
                for (int i = 0; i < 3; ++i) {
                    int idx = pid + 64 * i;
                    if (idx < 144) dst[idx] = src[idx];
                }
            }
            PAIR_BAR();
        }
    }
}

// ---------------------------------------------------------------------------
extern "C" void kernel_launch(void* const* d_in, const int* in_sizes, int n_in,
                              void* d_out, int out_size)
{
    const float* X    = (const float*)d_in[0];
    const float* dist = (const float*)d_in[1];
    const int*   nb   = (const int*)d_in[2];
    const float* WIa  = (const float*)d_in[3];
    const float* WAa  = (const float*)d_in[4];
    const float* WSa  = (const float*)d_in[5];
    const float* WIb  = (const float*)d_in[6];
    const float* WAb  = (const float*)d_in[7];
    const float* WSb  = (const float*)d_in[8];
    const float* Wd   = (const float*)d_in[9];
    const float* bd   = (const float*)d_in[10];
    float* out = (float*)d_out;

    int N = in_sizes[0] / 576;
    int E = in_sizes[1];

    void* phi_ptr = nullptr;
    void* env_ptr = nullptr;
    cudaGetSymbolAddress(&phi_ptr, g_PHI);
    cudaGetSymbolAddress(&env_ptr, g_ENV);
    cudaMemsetAsync(phi_ptr, 0, sizeof(float) * (size_t)N * 32, 0);
    cudaMemsetAsync(env_ptr, 0, sizeof(float) * (size_t)N, 0);

    double e5    = exp(-5.0);
    double delta = (1.0 - e5) / 31.0;
    double bb    = (2.0 / 32.0) * (1.0 - e5);
    double beta  = 1.0 / (bb * bb);
    float  c2    = (float)(2.0 * beta * delta);
    float  qf    = (float)exp(-2.0 * beta * delta * delta);

    // weight repack (order: WAa WSa WIa WAb WSb WIb)
    wq_kernel<<<6, 1024>>>(WAa, WSa, WIa, WAb, WSb, WIb);
    edge_kernel<<<(E + 255) / 256, 256>>>(dist, nb, E,
        (float)e5, (float)delta, (float)(1.0 / delta), (float)beta, c2, qf);
    coeff_kernel<<<(N + COEFF_NB - 1) / COEFF_NB, 192>>>(Wd, bd, N);

    node_kernel<<<444, 256, SMEM_FLOATS * sizeof(float)>>>(X, out, N);
}